// round 6
// baseline (speedup 1.0000x reference)
#include <cuda_runtime.h>
#include <cstdint>

#define NB 2
#define NT 2048
#define ND 1024
#define NH 16
#define NHD 64
#define NM (NB * NT) /* 4096 rows */

// Scratch (device globals: allocation-free per harness rules)
__device__ float g_q[(size_t)NB * NH * NT * NHD];
__device__ float g_k[(size_t)NB * NH * NT * NHD];
__device__ float g_v[(size_t)NB * NH * NT * NHD];
__device__ float g_y[(size_t)NM * ND];

// ---------------------------------------------------------------------------
// tf32 / math helpers
// ---------------------------------------------------------------------------
__device__ __forceinline__ uint32_t f2tf32(float x) {
    uint32_t r;
    asm("cvt.rna.tf32.f32 %0, %1;" : "=r"(r) : "f"(x));
    return r;
}

__device__ __forceinline__ float ex2(float x) {
    float y;
    asm("ex2.approx.ftz.f32 %0, %1;" : "=f"(y) : "f"(x));
    return y;
}

__device__ __forceinline__ void mma_tf32(float* c, const uint32_t* a,
                                         const uint32_t* b) {
    asm volatile(
        "mma.sync.aligned.m16n8k8.row.col.f32.tf32.tf32.f32 "
        "{%0,%1,%2,%3}, {%4,%5,%6,%7}, {%8,%9}, {%0,%1,%2,%3};\n"
        : "+f"(c[0]), "+f"(c[1]), "+f"(c[2]), "+f"(c[3])
        : "r"(a[0]), "r"(a[1]), "r"(a[2]), "r"(a[3]), "r"(b[0]), "r"(b[1]));
}

// ---------------------------------------------------------------------------
// tf32 tensor-core GEMM, double-buffered: C[m,n] = A[m,:]·W[n,:] + bias[n]
// 128x128 tile, K-step 16, 256 threads (8 warps, 2x4), warp tile 64x32.
// One __syncthreads per K-step; LDG for tile k+1 overlaps MMA on tile k.
// ---------------------------------------------------------------------------
#define BKP 20

template <bool HEADS>
__global__ __launch_bounds__(256, 2)
void gemm_kernel(const float* __restrict__ A,
                 const float* __restrict__ W0, const float* __restrict__ B0,
                 const float* __restrict__ W1, const float* __restrict__ B1,
                 const float* __restrict__ W2, const float* __restrict__ B2,
                 float* __restrict__ Cplain)
{
    const float* W;
    const float* bias;
    float* outq = nullptr;
    if (HEADS) {
        int z = blockIdx.z;
        W    = (z == 0) ? W0 : (z == 1) ? W1 : W2;
        bias = (z == 0) ? B0 : (z == 1) ? B1 : B2;
        outq = (z == 0) ? g_q : (z == 1) ? g_k : g_v;
    } else {
        W = W0; bias = B0;
    }
    const float* Ap = HEADS ? A : g_y;

    __shared__ uint32_t As[2][128][BKP];
    __shared__ uint32_t Bs[2][128][BKP];

    const int tid  = threadIdx.x;
    const int lane = tid & 31;
    const int wid  = tid >> 5;
    const int m0 = blockIdx.y * 128;
    const int n0 = blockIdx.x * 128;
    const int warp_m = (wid >> 2) * 64;
    const int warp_n = (wid & 3) * 32;

    const int r0 = tid >> 2;
    const int c4 = (tid & 3) * 4;

    float acc[4][4][4];
#pragma unroll
    for (int mi = 0; mi < 4; mi++)
#pragma unroll
        for (int ni = 0; ni < 4; ni++)
#pragma unroll
            for (int r = 0; r < 4; r++) acc[mi][ni][r] = 0.f;

    const float* aBase = Ap + (size_t)m0 * ND;
    const float* wBase = W  + (size_t)n0 * ND;

    // preload tile k=0 and stage to buffer 0
    float4 pa0 = *(const float4*)(aBase + (size_t)r0 * ND + c4);
    float4 pa1 = *(const float4*)(aBase + (size_t)(r0 + 64) * ND + c4);
    float4 pb0 = *(const float4*)(wBase + (size_t)r0 * ND + c4);
    float4 pb1 = *(const float4*)(wBase + (size_t)(r0 + 64) * ND + c4);
    {
        uint4 u;
        u.x = f2tf32(pa0.x); u.y = f2tf32(pa0.y);
        u.z = f2tf32(pa0.z); u.w = f2tf32(pa0.w);
        *(uint4*)&As[0][r0][c4] = u;
        u.x = f2tf32(pa1.x); u.y = f2tf32(pa1.y);
        u.z = f2tf32(pa1.z); u.w = f2tf32(pa1.w);
        *(uint4*)&As[0][r0 + 64][c4] = u;
        u.x = f2tf32(pb0.x); u.y = f2tf32(pb0.y);
        u.z = f2tf32(pb0.z); u.w = f2tf32(pb0.w);
        *(uint4*)&Bs[0][r0][c4] = u;
        u.x = f2tf32(pb1.x); u.y = f2tf32(pb1.y);
        u.z = f2tf32(pb1.z); u.w = f2tf32(pb1.w);
        *(uint4*)&Bs[0][r0 + 64][c4] = u;
    }
    __syncthreads();

    int buf = 0;
    for (int k0 = 0; k0 < ND; k0 += 16) {
        const bool more = (k0 + 16 < ND);
        if (more) {
            const int kn = k0 + 16;
            pa0 = *(const float4*)(aBase + (size_t)r0 * ND + kn + c4);
            pa1 = *(const float4*)(aBase + (size_t)(r0 + 64) * ND + kn + c4);
            pb0 = *(const float4*)(wBase + (size_t)r0 * ND + kn + c4);
            pb1 = *(const float4*)(wBase + (size_t)(r0 + 64) * ND + kn + c4);
        }

#pragma unroll
        for (int t = 0; t < 2; t++) {
            const int kk = t * 8 + (lane & 3);
            uint32_t afr[4][4], bfr[4][2];
#pragma unroll
            for (int mi = 0; mi < 4; mi++) {
                int r = warp_m + mi * 16 + (lane >> 2);
                afr[mi][0] = As[buf][r][kk];
                afr[mi][1] = As[buf][r + 8][kk];
                afr[mi][2] = As[buf][r][kk + 4];
                afr[mi][3] = As[buf][r + 8][kk + 4];
            }
#pragma unroll
            for (int ni = 0; ni < 4; ni++) {
                int c = warp_n + ni * 8 + (lane >> 2);
                bfr[ni][0] = Bs[buf][c][kk];
                bfr[ni][1] = Bs[buf][c][kk + 4];
            }
#pragma unroll
            for (int mi = 0; mi < 4; mi++)
#pragma unroll
                for (int ni = 0; ni < 4; ni++)
                    mma_tf32(acc[mi][ni], afr[mi], bfr[ni]);
        }

        if (more) {
            const int nb = buf ^ 1;
            uint4 u;
            u.x = f2tf32(pa0.x); u.y = f2tf32(pa0.y);
            u.z = f2tf32(pa0.z); u.w = f2tf32(pa0.w);
            *(uint4*)&As[nb][r0][c4] = u;
            u.x = f2tf32(pa1.x); u.y = f2tf32(pa1.y);
            u.z = f2tf32(pa1.z); u.w = f2tf32(pa1.w);
            *(uint4*)&As[nb][r0 + 64][c4] = u;
            u.x = f2tf32(pb0.x); u.y = f2tf32(pb0.y);
            u.z = f2tf32(pb0.z); u.w = f2tf32(pb0.w);
            *(uint4*)&Bs[nb][r0][c4] = u;
            u.x = f2tf32(pb1.x); u.y = f2tf32(pb1.y);
            u.z = f2tf32(pb1.z); u.w = f2tf32(pb1.w);
            *(uint4*)&Bs[nb][r0 + 64][c4] = u;
            __syncthreads();
            buf = nb;
        }
    }

#pragma unroll
    for (int mi = 0; mi < 4; mi++) {
#pragma unroll
        for (int ni = 0; ni < 4; ni++) {
#pragma unroll
            for (int half = 0; half < 2; half++) {
                int m = m0 + warp_m + mi * 16 + (lane >> 2) + half * 8;
                int nA = n0 + warp_n + ni * 8 + 2 * (lane & 3);
                float v0 = acc[mi][ni][half * 2 + 0] + bias[nA];
                float v1 = acc[mi][ni][half * 2 + 1] + bias[nA + 1];
                if (HEADS) {
                    int bb = m >> 11;
                    int tt = m & (NT - 1);
                    int h  = nA >> 6;
                    int hd = nA & (NHD - 1);
                    float* dst = outq +
                        (((size_t)bb * NH + h) * NT + tt) * NHD + hd;
                    dst[0] = v0; dst[1] = v1;
                } else {
                    float* dst = Cplain + (size_t)m * ND + nA;
                    dst[0] = v0; dst[1] = v1;
                }
            }
        }
    }
}

// ---------------------------------------------------------------------------
// Tensor-core tf32 flash attention, causal, double-buffered K/V tiles.
// CTA: 128 q rows, 8 warps x 16 rows. K/V in smem (natural [key][dim],
// stride 72 words). One __syncthreads per tile; next tile's LDGs overlap
// this tile's MMAs. P round-trips via warp-private smem slab (syncwarp).
// ---------------------------------------------------------------------------
#define AST 72  /* smem row stride in words */
/* layout: K0,K1,V0,V1 (64 rows each), Ps (128 rows) */
#define ATTN_SMEM ((4 * 64 + 128) * AST * 4)  /* 110592 B */

__global__ __launch_bounds__(256)
void attn_tc_kernel()
{
    extern __shared__ uint32_t smraw[];
    uint32_t* KsB[2] = { smraw,            smraw + 64 * AST };
    uint32_t* VsB[2] = { smraw + 128 * AST, smraw + 192 * AST };
    uint32_t (*Ps)[AST] = (uint32_t(*)[AST])(smraw + 256 * AST);

    const int bh   = blockIdx.y;
    const int q0   = blockIdx.x * 128;
    const int tid  = threadIdx.x;
    const int lane = tid & 31;
    const int warp = tid >> 5;
    const int r    = lane >> 2;    // 0..7
    const int c    = lane & 3;     // 0..3
    const int w16  = warp * 16;

    const float* Qb = g_q + (size_t)bh * NT * NHD;
    const float* Kb = g_k + (size_t)bh * NT * NHD;
    const float* Vb = g_v + (size_t)bh * NT * NHD;

    // ---- stage Q tile through Ps, pull A-fragments into registers ----
#pragma unroll
    for (int i = 0; i < 8; i++) {
        int idx = tid + i * 256;        // 0..2047
        int row = idx >> 4;             // 0..127
        int c4  = (idx & 15) * 4;
        float4 v = *(const float4*)(Qb + (size_t)(q0 + row) * NHD + c4);
        uint4 u;
        u.x = f2tf32(v.x); u.y = f2tf32(v.y);
        u.z = f2tf32(v.z); u.w = f2tf32(v.w);
        *(uint4*)&Ps[row][c4] = u;
    }
    __syncthreads();

    uint32_t qf[8][4];
#pragma unroll
    for (int kc = 0; kc < 8; kc++) {
        qf[kc][0] = Ps[w16 + r][kc * 8 + c];
        qf[kc][1] = Ps[w16 + r + 8][kc * 8 + c];
        qf[kc][2] = Ps[w16 + r][kc * 8 + c + 4];
        qf[kc][3] = Ps[w16 + r + 8][kc * 8 + c + 4];
    }
    __syncthreads();

    float o[8][4];
#pragma unroll
    for (int nt = 0; nt < 8; nt++)
#pragma unroll
        for (int e = 0; e < 4; e++) o[nt][e] = 0.f;

    float m0 = -1e30f, m1 = -1e30f, l0 = 0.f, l1 = 0.f;
    const int grow0 = q0 + w16 + r;
    const int grow1 = grow0 + 8;
    const float C2 = 0.18033688f;   // 0.125 * log2(e)

    // per-thread global->smem mapping for K/V tiles (4 float4 each)
    const int lrow = tid >> 4;            // 0..15 base row
    const int lc4  = (tid & 15) * 4;      // col group... (recomputed per i)

    (void)lrow; (void)lc4;

    const int ktiles = blockIdx.x * 2 + 2;

    // ---- prefetch tile 0 into registers, stage into buffer 0 ----
    float4 kst[4], vst[4];
#pragma unroll
    for (int i = 0; i < 4; i++) {
        int idx = tid + i * 256;    // 0..1023
        int row = idx >> 4;         // 0..63
        int c4  = (idx & 15) * 4;
        kst[i] = *(const float4*)(Kb + (size_t)row * NHD + c4);
        vst[i] = *(const float4*)(Vb + (size_t)row * NHD + c4);
    }
#pragma unroll
    for (int i = 0; i < 4; i++) {
        int idx = tid + i * 256;
        int row = idx >> 4;
        int c4  = (idx & 15) * 4;
        uint4 u;
        u.x = f2tf32(kst[i].x); u.y = f2tf32(kst[i].y);
        u.z = f2tf32(kst[i].z); u.w = f2tf32(kst[i].w);
        *(uint4*)&KsB[0][row * AST + c4] = u;
        u.x = f2tf32(vst[i].x); u.y = f2tf32(vst[i].y);
        u.z = f2tf32(vst[i].z); u.w = f2tf32(vst[i].w);
        *(uint4*)&VsB[0][row * AST + c4] = u;
    }
    __syncthreads();

    for (int kt = 0; kt < ktiles; kt++) {
        const int kbase = kt * 64;
        const int buf = kt & 1;
        const bool more = (kt + 1 < ktiles);
        const uint32_t* Kc = KsB[buf];
        const uint32_t* Vc = VsB[buf];

        // issue LDGs for next tile (latency hidden behind MMAs below)
        if (more) {
            const int nb0 = kbase + 64;
#pragma unroll
            for (int i = 0; i < 4; i++) {
                int idx = tid + i * 256;
                int row = idx >> 4;
                int c4  = (idx & 15) * 4;
                kst[i] = *(const float4*)(Kb + (size_t)(nb0 + row) * NHD + c4);
                vst[i] = *(const float4*)(Vb + (size_t)(nb0 + row) * NHD + c4);
            }
        }

        // ---- S = Q @ K^T  (warp's 16 rows x 64 keys) ----
        float sfr[8][4];
#pragma unroll
        for (int nt = 0; nt < 8; nt++) {
            sfr[nt][0] = sfr[nt][1] = sfr[nt][2] = sfr[nt][3] = 0.f;
#pragma unroll
            for (int kc = 0; kc < 8; kc++) {
                uint32_t b[2];
                b[0] = Kc[(nt * 8 + r) * AST + kc * 8 + c];
                b[1] = Kc[(nt * 8 + r) * AST + kc * 8 + c + 4];
                mma_tf32(sfr[nt], qf[kc], b);
            }
        }

        // ---- causal mask (only diagonal tiles of this warp) ----
        if (kbase + 63 > q0 + w16) {
#pragma unroll
            for (int nt = 0; nt < 8; nt++) {
                int col = kbase + nt * 8 + 2 * c;
                if (col > grow0)     sfr[nt][0] = -1e30f;
                if (col + 1 > grow0) sfr[nt][1] = -1e30f;
                if (col > grow1)     sfr[nt][2] = -1e30f;
                if (col + 1 > grow1) sfr[nt][3] = -1e30f;
            }
        }

        // ---- online softmax ----
        float mx0 = -1e30f, mx1 = -1e30f;
#pragma unroll
        for (int nt = 0; nt < 8; nt++) {
            mx0 = fmaxf(mx0, fmaxf(sfr[nt][0], sfr[nt][1]));
            mx1 = fmaxf(mx1, fmaxf(sfr[nt][2], sfr[nt][3]));
        }
        mx0 = fmaxf(mx0, __shfl_xor_sync(0xffffffffu, mx0, 1));
        mx0 = fmaxf(mx0, __shfl_xor_sync(0xffffffffu, mx0, 2));
        mx1 = fmaxf(mx1, __shfl_xor_sync(0xffffffffu, mx1, 1));
        mx1 = fmaxf(mx1, __shfl_xor_sync(0xffffffffu, mx1, 2));

        float mn0 = fmaxf(m0, mx0);
        float mn1 = fmaxf(m1, mx1);
        float cor0 = ex2((m0 - mn0) * C2);
        float cor1 = ex2((m1 - mn1) * C2);
        l0 *= cor0; l1 *= cor1;
        m0 = mn0;   m1 = mn1;

#pragma unroll
        for (int nt = 0; nt < 8; nt++) {
            float p0 = ex2((sfr[nt][0] - mn0) * C2);
            float p1 = ex2((sfr[nt][1] - mn0) * C2);
            float p2 = ex2((sfr[nt][2] - mn1) * C2);
            float p3 = ex2((sfr[nt][3] - mn1) * C2);
            l0 += p0 + p1;
            l1 += p2 + p3;
            o[nt][0] *= cor0; o[nt][1] *= cor0;
            o[nt][2] *= cor1; o[nt][3] *= cor1;
            uint2 w0; w0.x = f2tf32(p0); w0.y = f2tf32(p1);
            *(uint2*)&Ps[w16 + r][nt * 8 + 2 * c] = w0;
            uint2 w1; w1.x = f2tf32(p2); w1.y = f2tf32(p3);
            *(uint2*)&Ps[w16 + r + 8][nt * 8 + 2 * c] = w1;
        }
        __syncwarp();   // P slab is warp-private: no CTA barrier needed

        // ---- O += P @ V ----
#pragma unroll
        for (int kc = 0; kc < 8; kc++) {
            uint32_t a[4];
            a[0] = Ps[w16 + r][kc * 8 + c];
            a[1] = Ps[w16 + r + 8][kc * 8 + c];
            a[2] = Ps[w16 + r][kc * 8 + c + 4];
            a[3] = Ps[w16 + r + 8][kc * 8 + c + 4];
#pragma unroll
            for (int nt = 0; nt < 8; nt++) {
                uint32_t b[2];
                b[0] = Vc[(kc * 8 + c) * AST + nt * 8 + r];
                b[1] = Vc[(kc * 8 + c + 4) * AST + nt * 8 + r];
                mma_tf32(o[nt], a, b);
            }
        }
        __syncwarp();

        // ---- stage next tile into the other buffer, single barrier ----
        if (more) {
            uint32_t* Kn = KsB[buf ^ 1];
            uint32_t* Vn = VsB[buf ^ 1];
#pragma unroll
            for (int i = 0; i < 4; i++) {
                int idx = tid + i * 256;
                int row = idx >> 4;
                int c4  = (idx & 15) * 4;
                uint4 u;
                u.x = f2tf32(kst[i].x); u.y = f2tf32(kst[i].y);
                u.z = f2tf32(kst[i].z); u.w = f2tf32(kst[i].w);
                *(uint4*)&Kn[row * AST + c4] = u;
                u.x = f2tf32(vst[i].x); u.y = f2tf32(vst[i].y);
                u.z = f2tf32(vst[i].z); u.w = f2tf32(vst[i].w);
                *(uint4*)&Vn[row * AST + c4] = u;
            }
            __syncthreads();
        }
    }

    // ---- quad-reduce softmax denominators (per-thread partials) ----
    l0 += __shfl_xor_sync(0xffffffffu, l0, 1);
    l0 += __shfl_xor_sync(0xffffffffu, l0, 2);
    l1 += __shfl_xor_sync(0xffffffffu, l1, 1);
    l1 += __shfl_xor_sync(0xffffffffu, l1, 2);

    // ---- normalize + store ----
    const int b  = bh >> 4;
    const int h  = bh & (NH - 1);
    float inv0 = 1.f / l0;
    float inv1 = 1.f / l1;
    float* y0 = g_y + ((size_t)b * NT + grow0) * ND + h * NHD;
    float* y1 = g_y + ((size_t)b * NT + grow1) * ND + h * NHD;
#pragma unroll
    for (int nt = 0; nt < 8; nt++) {
        float2 w0; w0.x = o[nt][0] * inv0; w0.y = o[nt][1] * inv0;
        *(float2*)(y0 + nt * 8 + 2 * c) = w0;
        float2 w1; w1.x = o[nt][2] * inv1; w1.y = o[nt][3] * inv1;
        *(float2*)(y1 + nt * 8 + 2 * c) = w1;
    }
}

// ---------------------------------------------------------------------------
extern "C" void kernel_launch(void* const* d_in, const int* in_sizes, int n_in,
                              void* d_out, int out_size)
{
    const float* x  = (const float*)d_in[0];
    const float* Wq = (const float*)d_in[1];
    const float* bq = (const float*)d_in[2];
    const float* Wk = (const float*)d_in[3];
    const float* bk = (const float*)d_in[4];
    const float* Wv = (const float*)d_in[5];
    const float* bv = (const float*)d_in[6];
    const float* Wp = (const float*)d_in[7];
    const float* bp = (const float*)d_in[8];
    float* out = (float*)d_out;

    cudaFuncSetAttribute(attn_tc_kernel,
                         cudaFuncAttributeMaxDynamicSharedMemorySize,
                         ATTN_SMEM);

    dim3 gq(ND / 128, NM / 128, 3);   // 8 x 32 x 3
    gemm_kernel<true><<<gq, 256>>>(x, Wq, bq, Wk, bk, Wv, bv, nullptr);

    dim3 ga(NT / 128, NB * NH);       // 16 x 32
    attn_tc_kernel<<<ga, 256, ATTN_SMEM>>>();

    dim3 gp(ND / 128, NM / 128, 1);   // 8 x 32
    gemm_kernel<false><<<gp, 256>>>(nullptr, Wp, bp, nullptr, nullptr,
                                    nullptr, nullptr, out);
}

// round 7
// speedup vs baseline: 1.0938x; 1.0938x over previous
#include <cuda_runtime.h>
#include <cstdint>

#define NB 2
#define NT 2048
#define ND 1024
#define NH 16
#define NHD 64
#define NM (NB * NT) /* 4096 rows */

// Scratch (device globals: allocation-free per harness rules)
__device__ float g_q[(size_t)NB * NH * NT * NHD];
__device__ float g_k[(size_t)NB * NH * NT * NHD];
__device__ float g_v[(size_t)NB * NH * NT * NHD];
__device__ float g_y[(size_t)NM * ND];

// ---------------------------------------------------------------------------
// tf32 / math helpers
// ---------------------------------------------------------------------------
__device__ __forceinline__ uint32_t f2tf32(float x) {
    uint32_t r;
    asm("cvt.rna.tf32.f32 %0, %1;" : "=r"(r) : "f"(x));
    return r;
}

__device__ __forceinline__ float ex2(float x) {
    float y;
    asm("ex2.approx.ftz.f32 %0, %1;" : "=f"(y) : "f"(x));
    return y;
}

__device__ __forceinline__ void mma_tf32(float* c, const uint32_t* a,
                                         const uint32_t* b) {
    asm volatile(
        "mma.sync.aligned.m16n8k8.row.col.f32.tf32.tf32.f32 "
        "{%0,%1,%2,%3}, {%4,%5,%6,%7}, {%8,%9}, {%0,%1,%2,%3};\n"
        : "+f"(c[0]), "+f"(c[1]), "+f"(c[2]), "+f"(c[3])
        : "r"(a[0]), "r"(a[1]), "r"(a[2]), "r"(a[3]), "r"(b[0]), "r"(b[1]));
}

// ---------------------------------------------------------------------------
// tf32 tensor-core GEMM: C[m,n] = A[m,:]·W[n,:] + bias[n]
// CTA tile 128x128, K-step 16, 128 threads (4 warps, 2x2), warp tile 64x64.
// Warp tile widened 64x32 -> 64x64: smem FLOP/byte 10.7 -> 16 (R6 ncu showed
// L1=68%/tensor=36%: shared-memory-BW-bound). R5 single-buffer pipeline.
// ---------------------------------------------------------------------------
#define BKP 20

template <bool HEADS>
__global__ __launch_bounds__(128, 2)
void gemm_kernel(const float* __restrict__ A,
                 const float* __restrict__ W0, const float* __restrict__ B0,
                 const float* __restrict__ W1, const float* __restrict__ B1,
                 const float* __restrict__ W2, const float* __restrict__ B2,
                 float* __restrict__ Cplain)
{
    const float* W;
    const float* bias;
    float* outq = nullptr;
    if (HEADS) {
        int z = blockIdx.z;
        W    = (z == 0) ? W0 : (z == 1) ? W1 : W2;
        bias = (z == 0) ? B0 : (z == 1) ? B1 : B2;
        outq = (z == 0) ? g_q : (z == 1) ? g_k : g_v;
    } else {
        W = W0; bias = B0;
    }
    const float* Ap = HEADS ? A : g_y;

    __shared__ uint32_t As[128][BKP];
    __shared__ uint32_t Bs[128][BKP];

    const int tid  = threadIdx.x;
    const int lane = tid & 31;
    const int wid  = tid >> 5;
    const int m0 = blockIdx.y * 128;
    const int n0 = blockIdx.x * 128;
    const int warp_m = (wid >> 1) * 64;   // 0 or 64
    const int warp_n = (wid & 1) * 64;    // 0 or 64
    const int r = lane >> 2;              // 0..7
    const int qc = lane & 3;              // 0..3

    // global->smem staging: 512 float4 per tile, 4 per thread
    // idx = tid + i*128 -> row = idx>>2 (0..127), col4 = (idx&3)*4
    float acc[4][8][4];
#pragma unroll
    for (int mi = 0; mi < 4; mi++)
#pragma unroll
        for (int ni = 0; ni < 8; ni++)
#pragma unroll
            for (int e = 0; e < 4; e++) acc[mi][ni][e] = 0.f;

    const float* aBase = Ap + (size_t)m0 * ND;
    const float* wBase = W  + (size_t)n0 * ND;

    float4 pa[4], pb[4];
#pragma unroll
    for (int i = 0; i < 4; i++) {
        int idx = tid + i * 128;
        int row = idx >> 2;
        int c4  = (idx & 3) * 4;
        pa[i] = *(const float4*)(aBase + (size_t)row * ND + c4);
        pb[i] = *(const float4*)(wBase + (size_t)row * ND + c4);
    }

    for (int k0 = 0; k0 < ND; k0 += 16) {
        __syncthreads();   // previous compute done before overwrite
#pragma unroll
        for (int i = 0; i < 4; i++) {
            int idx = tid + i * 128;
            int row = idx >> 2;
            int c4  = (idx & 3) * 4;
            uint4 u;
            u.x = f2tf32(pa[i].x); u.y = f2tf32(pa[i].y);
            u.z = f2tf32(pa[i].z); u.w = f2tf32(pa[i].w);
            *(uint4*)&As[row][c4] = u;
            u.x = f2tf32(pb[i].x); u.y = f2tf32(pb[i].y);
            u.z = f2tf32(pb[i].z); u.w = f2tf32(pb[i].w);
            *(uint4*)&Bs[row][c4] = u;
        }
        __syncthreads();

        if (k0 + 16 < ND) {
            const int kn = k0 + 16;
#pragma unroll
            for (int i = 0; i < 4; i++) {
                int idx = tid + i * 128;
                int row = idx >> 2;
                int c4  = (idx & 3) * 4;
                pa[i] = *(const float4*)(aBase + (size_t)row * ND + kn + c4);
                pb[i] = *(const float4*)(wBase + (size_t)row * ND + kn + c4);
            }
        }

#pragma unroll
        for (int t = 0; t < 2; t++) {
            const int kk = t * 8 + qc;
            uint32_t afr[4][4], bfr[8][2];
#pragma unroll
            for (int mi = 0; mi < 4; mi++) {
                int rr = warp_m + mi * 16 + r;
                afr[mi][0] = As[rr][kk];
                afr[mi][1] = As[rr + 8][kk];
                afr[mi][2] = As[rr][kk + 4];
                afr[mi][3] = As[rr + 8][kk + 4];
            }
#pragma unroll
            for (int ni = 0; ni < 8; ni++) {
                int cc = warp_n + ni * 8 + r;
                bfr[ni][0] = Bs[cc][kk];
                bfr[ni][1] = Bs[cc][kk + 4];
            }
#pragma unroll
            for (int mi = 0; mi < 4; mi++)
#pragma unroll
                for (int ni = 0; ni < 8; ni++)
                    mma_tf32(acc[mi][ni], afr[mi], bfr[ni]);
        }
    }

#pragma unroll
    for (int mi = 0; mi < 4; mi++) {
#pragma unroll
        for (int ni = 0; ni < 8; ni++) {
#pragma unroll
            for (int half = 0; half < 2; half++) {
                int m = m0 + warp_m + mi * 16 + r + half * 8;
                int nA = n0 + warp_n + ni * 8 + 2 * qc;
                float v0 = acc[mi][ni][half * 2 + 0] + bias[nA];
                float v1 = acc[mi][ni][half * 2 + 1] + bias[nA + 1];
                if (HEADS) {
                    int bb = m >> 11;
                    int tt = m & (NT - 1);
                    int h  = nA >> 6;
                    int hd = nA & (NHD - 1);
                    float* dst = outq +
                        (((size_t)bb * NH + h) * NT + tt) * NHD + hd;
                    dst[0] = v0; dst[1] = v1;
                } else {
                    float* dst = Cplain + (size_t)m * ND + nA;
                    dst[0] = v0; dst[1] = v1;
                }
            }
        }
    }
}

// ---------------------------------------------------------------------------
// Tensor-core tf32 flash attention, causal (R5 version, verbatim revert).
// CTA: 128 q rows, 8 warps x 16 rows. 64-key K/V tiles in smem (natural
// [key][dim] layout, stride 72 words -> all fragment reads conflict-free).
// P round-trips through warp-private smem slab (syncwarp only).
// ---------------------------------------------------------------------------
#define AST 72  /* smem row stride in words */
#define ATTN_SMEM ((64 + 64 + 128) * AST * 4)  /* 73728 B */

__global__ __launch_bounds__(256)
void attn_tc_kernel()
{
    extern __shared__ uint32_t smraw[];
    uint32_t (*Ks)[AST] = (uint32_t(*)[AST])smraw;
    uint32_t (*Vs)[AST] = (uint32_t(*)[AST])(smraw + 64 * AST);
    uint32_t (*Ps)[AST] = (uint32_t(*)[AST])(smraw + 128 * AST);

    const int bh   = blockIdx.y;
    const int q0   = blockIdx.x * 128;
    const int tid  = threadIdx.x;
    const int lane = tid & 31;
    const int warp = tid >> 5;
    const int r    = lane >> 2;    // 0..7
    const int c    = lane & 3;     // 0..3
    const int w16  = warp * 16;

    const float* Qb = g_q + (size_t)bh * NT * NHD;
    const float* Kb = g_k + (size_t)bh * NT * NHD;
    const float* Vb = g_v + (size_t)bh * NT * NHD;

    // ---- stage Q tile through Ps, pull A-fragments into registers ----
#pragma unroll
    for (int i = 0; i < 8; i++) {
        int idx = tid + i * 256;        // 0..2047
        int row = idx >> 4;             // 0..127
        int c4  = (idx & 15) * 4;
        float4 v = *(const float4*)(Qb + (size_t)(q0 + row) * NHD + c4);
        uint4 u;
        u.x = f2tf32(v.x); u.y = f2tf32(v.y);
        u.z = f2tf32(v.z); u.w = f2tf32(v.w);
        *(uint4*)&Ps[row][c4] = u;
    }
    __syncthreads();

    uint32_t qf[8][4];
#pragma unroll
    for (int kc = 0; kc < 8; kc++) {
        qf[kc][0] = Ps[w16 + r][kc * 8 + c];
        qf[kc][1] = Ps[w16 + r + 8][kc * 8 + c];
        qf[kc][2] = Ps[w16 + r][kc * 8 + c + 4];
        qf[kc][3] = Ps[w16 + r + 8][kc * 8 + c + 4];
    }
    __syncthreads();

    float o[8][4];
#pragma unroll
    for (int nt = 0; nt < 8; nt++)
#pragma unroll
        for (int e = 0; e < 4; e++) o[nt][e] = 0.f;

    float m0 = -1e30f, m1 = -1e30f, l0 = 0.f, l1 = 0.f;
    const int grow0 = q0 + w16 + r;
    const int grow1 = grow0 + 8;
    const float C2 = 0.18033688f;   // 0.125 * log2(e)

    const int ktiles = blockIdx.x * 2 + 2;
    for (int kt = 0; kt < ktiles; kt++) {
        const int kbase = kt * 64;
        __syncthreads();   // all warps done reading Ks/Vs from prev iter
#pragma unroll
        for (int i = 0; i < 4; i++) {
            int idx = tid + i * 256;    // 0..1023
            int row = idx >> 4;         // 0..63
            int c4  = (idx & 15) * 4;
            float4 kv = *(const float4*)(Kb + (size_t)(kbase + row) * NHD + c4);
            float4 vv = *(const float4*)(Vb + (size_t)(kbase + row) * NHD + c4);
            uint4 u;
            u.x = f2tf32(kv.x); u.y = f2tf32(kv.y);
            u.z = f2tf32(kv.z); u.w = f2tf32(kv.w);
            *(uint4*)&Ks[row][c4] = u;
            u.x = f2tf32(vv.x); u.y = f2tf32(vv.y);
            u.z = f2tf32(vv.z); u.w = f2tf32(vv.w);
            *(uint4*)&Vs[row][c4] = u;
        }
        __syncthreads();

        // ---- S = Q @ K^T  (warp's 16 rows x 64 keys) ----
        float sfr[8][4];
#pragma unroll
        for (int nt = 0; nt < 8; nt++) {
            sfr[nt][0] = sfr[nt][1] = sfr[nt][2] = sfr[nt][3] = 0.f;
#pragma unroll
            for (int kc = 0; kc < 8; kc++) {
                uint32_t b[2];
                b[0] = Ks[nt * 8 + r][kc * 8 + c];
                b[1] = Ks[nt * 8 + r][kc * 8 + c + 4];
                mma_tf32(sfr[nt], qf[kc], b);
            }
        }

        // ---- causal mask (only diagonal tiles of this warp) ----
        if (kbase + 63 > q0 + w16) {
#pragma unroll
            for (int nt = 0; nt < 8; nt++) {
                int col = kbase + nt * 8 + 2 * c;
                if (col > grow0)     sfr[nt][0] = -1e30f;
                if (col + 1 > grow0) sfr[nt][1] = -1e30f;
                if (col > grow1)     sfr[nt][2] = -1e30f;
                if (col + 1 > grow1) sfr[nt][3] = -1e30f;
            }
        }

        // ---- online softmax ----
        float mx0 = -1e30f, mx1 = -1e30f;
#pragma unroll
        for (int nt = 0; nt < 8; nt++) {
            mx0 = fmaxf(mx0, fmaxf(sfr[nt][0], sfr[nt][1]));
            mx1 = fmaxf(mx1, fmaxf(sfr[nt][2], sfr[nt][3]));
        }
        mx0 = fmaxf(mx0, __shfl_xor_sync(0xffffffffu, mx0, 1));
        mx0 = fmaxf(mx0, __shfl_xor_sync(0xffffffffu, mx0, 2));
        mx1 = fmaxf(mx1, __shfl_xor_sync(0xffffffffu, mx1, 1));
        mx1 = fmaxf(mx1, __shfl_xor_sync(0xffffffffu, mx1, 2));

        float mn0 = fmaxf(m0, mx0);
        float mn1 = fmaxf(m1, mx1);
        float cor0 = ex2((m0 - mn0) * C2);
        float cor1 = ex2((m1 - mn1) * C2);
        l0 *= cor0; l1 *= cor1;
        m0 = mn0;   m1 = mn1;

#pragma unroll
        for (int nt = 0; nt < 8; nt++) {
            float p0 = ex2((sfr[nt][0] - mn0) * C2);
            float p1 = ex2((sfr[nt][1] - mn0) * C2);
            float p2 = ex2((sfr[nt][2] - mn1) * C2);
            float p3 = ex2((sfr[nt][3] - mn1) * C2);
            l0 += p0 + p1;
            l1 += p2 + p3;
            o[nt][0] *= cor0; o[nt][1] *= cor0;
            o[nt][2] *= cor1; o[nt][3] *= cor1;
            uint2 w0; w0.x = f2tf32(p0); w0.y = f2tf32(p1);
            *(uint2*)&Ps[w16 + r][nt * 8 + 2 * c] = w0;
            uint2 w1; w1.x = f2tf32(p2); w1.y = f2tf32(p3);
            *(uint2*)&Ps[w16 + r + 8][nt * 8 + 2 * c] = w1;
        }
        __syncwarp();   // P slab is warp-private: no CTA barrier needed

        // ---- O += P @ V ----
#pragma unroll
        for (int kc = 0; kc < 8; kc++) {
            uint32_t a[4];
            a[0] = Ps[w16 + r][kc * 8 + c];
            a[1] = Ps[w16 + r + 8][kc * 8 + c];
            a[2] = Ps[w16 + r][kc * 8 + c + 4];
            a[3] = Ps[w16 + r + 8][kc * 8 + c + 4];
#pragma unroll
            for (int nt = 0; nt < 8; nt++) {
                uint32_t b[2];
                b[0] = Vs[kc * 8 + c][nt * 8 + r];
                b[1] = Vs[kc * 8 + c + 4][nt * 8 + r];
                mma_tf32(o[nt], a, b);
            }
        }
        __syncwarp();
    }

    // ---- quad-reduce softmax denominators (per-thread partials) ----
    l0 += __shfl_xor_sync(0xffffffffu, l0, 1);
    l0 += __shfl_xor_sync(0xffffffffu, l0, 2);
    l1 += __shfl_xor_sync(0xffffffffu, l1, 1);
    l1 += __shfl_xor_sync(0xffffffffu, l1, 2);

    // ---- normalize + store ----
    const int b  = bh >> 4;
    const int h  = bh & (NH - 1);
    float inv0 = 1.f / l0;
    float inv1 = 1.f / l1;
    float* y0 = g_y + ((size_t)b * NT + grow0) * ND + h * NHD;
    float* y1 = g_y + ((size_t)b * NT + grow1) * ND + h * NHD;
#pragma unroll
    for (int nt = 0; nt < 8; nt++) {
        float2 w0; w0.x = o[nt][0] * inv0; w0.y = o[nt][1] * inv0;
        *(float2*)(y0 + nt * 8 + 2 * c) = w0;
        float2 w1; w1.x = o[nt][2] * inv1; w1.y = o[nt][3] * inv1;
        *(float2*)(y1 + nt * 8 + 2 * c) = w1;
    }
}

// ---------------------------------------------------------------------------
extern "C" void kernel_launch(void* const* d_in, const int* in_sizes, int n_in,
                              void* d_out, int out_size)
{
    const float* x  = (const float*)d_in[0];
    const float* Wq = (const float*)d_in[1];
    const float* bq = (const float*)d_in[2];
    const float* Wk = (const float*)d_in[3];
    const float* bk = (const float*)d_in[4];
    const float* Wv = (const float*)d_in[5];
    const float* bv = (const float*)d_in[6];
    const float* Wp = (const float*)d_in[7];
    const float* bp = (const float*)d_in[8];
    float* out = (float*)d_out;

    cudaFuncSetAttribute(attn_tc_kernel,
                         cudaFuncAttributeMaxDynamicSharedMemorySize,
                         ATTN_SMEM);

    dim3 gq(ND / 128, NM / 128, 3);   // 8 x 32 x 3
    gemm_kernel<true><<<gq, 128>>>(x, Wq, bq, Wk, bk, Wv, bv, nullptr);

    dim3 ga(NT / 128, NB * NH);       // 16 x 32
    attn_tc_kernel<<<ga, 256, ATTN_SMEM>>>();

    dim3 gp(ND / 128, NM / 128, 1);   // 8 x 32
    gemm_kernel<false><<<gp, 128>>>(nullptr, Wp, bp, nullptr, nullptr,
                                    nullptr, nullptr, out);
}

// round 8
// speedup vs baseline: 1.2154x; 1.1112x over previous
#include <cuda_runtime.h>
#include <cstdint>

#define NB 2
#define NT 2048
#define ND 1024
#define NH 16
#define NHD 64
#define NM (NB * NT) /* 4096 rows */

// Scratch (device globals: allocation-free per harness rules)
__device__ float g_q[(size_t)NB * NH * NT * NHD];
__device__ float g_k[(size_t)NB * NH * NT * NHD];
__device__ float g_v[(size_t)NB * NH * NT * NHD];
__device__ float g_y[(size_t)NM * ND];

// ---------------------------------------------------------------------------
// tf32 / math helpers
// ---------------------------------------------------------------------------
__device__ __forceinline__ uint32_t f2tf32(float x) {
    uint32_t r;
    asm("cvt.rna.tf32.f32 %0, %1;" : "=r"(r) : "f"(x));
    return r;
}

__device__ __forceinline__ float ex2(float x) {
    float y;
    asm("ex2.approx.ftz.f32 %0, %1;" : "=f"(y) : "f"(x));
    return y;
}

__device__ __forceinline__ void mma_tf32(float* c, const uint32_t* a,
                                         const uint32_t* b) {
    asm volatile(
        "mma.sync.aligned.m16n8k8.row.col.f32.tf32.tf32.f32 "
        "{%0,%1,%2,%3}, {%4,%5,%6,%7}, {%8,%9}, {%0,%1,%2,%3};\n"
        : "+f"(c[0]), "+f"(c[1]), "+f"(c[2]), "+f"(c[3])
        : "r"(a[0]), "r"(a[1]), "r"(a[2]), "r"(a[3]), "r"(b[0]), "r"(b[1]));
}

// ldmatrix x4: four 8x8 b16 matrices == four 8x4 b32 matrices.
// addr is a shared-state-space byte address (per-lane row pointers).
__device__ __forceinline__ void ldsm_x4(uint32_t* d, uint32_t addr) {
    asm volatile(
        "ldmatrix.sync.aligned.m8n8.x4.shared.b16 {%0,%1,%2,%3}, [%4];"
        : "=r"(d[0]), "=r"(d[1]), "=r"(d[2]), "=r"(d[3])
        : "r"(addr));
}

// ---------------------------------------------------------------------------
// tf32 tensor-core GEMM: C[m,n] = A[m,:]·W[n,:] + bias[n]
// CTA tile 128x128, K-step 16, 128 threads (4 warps, 2x2), warp tile 64x64.
// R8: fragment loads via ldmatrix.x4 (8 LDSM per t-step instead of 48 LDS.32)
// — R7 ncu showed operand-delivery latency/issue bound (tensor 38.6%,
// issue 27.2%, occ 11.6%), not smem bytes. Natural layout + BKP=20 makes
// all LDSM line sets bank-conflict-free (20r mod 32 covers all banks).
// ---------------------------------------------------------------------------
#define BKP 20

template <bool HEADS>
__global__ __launch_bounds__(128, 2)
void gemm_kernel(const float* __restrict__ A,
                 const float* __restrict__ W0, const float* __restrict__ B0,
                 const float* __restrict__ W1, const float* __restrict__ B1,
                 const float* __restrict__ W2, const float* __restrict__ B2,
                 float* __restrict__ Cplain)
{
    const float* W;
    const float* bias;
    float* outq = nullptr;
    if (HEADS) {
        int z = blockIdx.z;
        W    = (z == 0) ? W0 : (z == 1) ? W1 : W2;
        bias = (z == 0) ? B0 : (z == 1) ? B1 : B2;
        outq = (z == 0) ? g_q : (z == 1) ? g_k : g_v;
    } else {
        W = W0; bias = B0;
    }
    const float* Ap = HEADS ? A : g_y;

    __shared__ uint32_t As[128][BKP];
    __shared__ uint32_t Bs[128][BKP];

    const int tid  = threadIdx.x;
    const int lane = tid & 31;
    const int wid  = tid >> 5;
    const int m0 = blockIdx.y * 128;
    const int n0 = blockIdx.x * 128;
    const int warp_m = (wid >> 1) * 64;   // 0 or 64
    const int warp_n = (wid & 1) * 64;    // 0 or 64
    const int r = lane >> 2;              // 0..7
    const int qc = lane & 3;              // 0..3

    // ldmatrix per-lane row addresses (byte offsets in shared space).
    // A x4 (per mi,t): groups g=lane>>3, lr=lane&7:
    //   row = warp_m + (g&1)*8 + lr, col = t*8 + (g>>1)*4
    // B x4 (per nj,t): row = warp_n + (g>>1)*8 + lr, col = t*8 + (g&1)*4
    const int g  = lane >> 3;
    const int lr = lane & 7;
    const uint32_t aBaseS =
        (uint32_t)__cvta_generic_to_shared(&As[0][0]);
    const uint32_t bBaseS =
        (uint32_t)__cvta_generic_to_shared(&Bs[0][0]);
    const uint32_t aAddr0 =
        aBaseS + (((warp_m + (g & 1) * 8 + lr) * BKP + (g >> 1) * 4) << 2);
    const uint32_t bAddr0 =
        bBaseS + (((warp_n + (g >> 1) * 8 + lr) * BKP + (g & 1) * 4) << 2);

    float acc[4][8][4];
#pragma unroll
    for (int mi = 0; mi < 4; mi++)
#pragma unroll
        for (int ni = 0; ni < 8; ni++)
#pragma unroll
            for (int e = 0; e < 4; e++) acc[mi][ni][e] = 0.f;

    const float* aBase = Ap + (size_t)m0 * ND;
    const float* wBase = W  + (size_t)n0 * ND;

    float4 pa[4], pb[4];
#pragma unroll
    for (int i = 0; i < 4; i++) {
        int idx = tid + i * 128;
        int row = idx >> 2;
        int c4  = (idx & 3) * 4;
        pa[i] = *(const float4*)(aBase + (size_t)row * ND + c4);
        pb[i] = *(const float4*)(wBase + (size_t)row * ND + c4);
    }

    for (int k0 = 0; k0 < ND; k0 += 16) {
        __syncthreads();   // previous compute done before overwrite
#pragma unroll
        for (int i = 0; i < 4; i++) {
            int idx = tid + i * 128;
            int row = idx >> 2;
            int c4  = (idx & 3) * 4;
            uint4 u;
            u.x = f2tf32(pa[i].x); u.y = f2tf32(pa[i].y);
            u.z = f2tf32(pa[i].z); u.w = f2tf32(pa[i].w);
            *(uint4*)&As[row][c4] = u;
            u.x = f2tf32(pb[i].x); u.y = f2tf32(pb[i].y);
            u.z = f2tf32(pb[i].z); u.w = f2tf32(pb[i].w);
            *(uint4*)&Bs[row][c4] = u;
        }
        __syncthreads();

        if (k0 + 16 < ND) {
            const int kn = k0 + 16;
#pragma unroll
            for (int i = 0; i < 4; i++) {
                int idx = tid + i * 128;
                int row = idx >> 2;
                int c4  = (idx & 3) * 4;
                pa[i] = *(const float4*)(aBase + (size_t)row * ND + kn + c4);
                pb[i] = *(const float4*)(wBase + (size_t)row * ND + kn + c4);
            }
        }

#pragma unroll
        for (int t = 0; t < 2; t++) {
            uint32_t afr[4][4], bfr[4][4];
#pragma unroll
            for (int mi = 0; mi < 4; mi++)
                ldsm_x4(afr[mi], aAddr0 + (uint32_t)(mi * 16 * BKP * 4 + t * 32));
#pragma unroll
            for (int nj = 0; nj < 4; nj++)
                ldsm_x4(bfr[nj], bAddr0 + (uint32_t)(nj * 16 * BKP * 4 + t * 32));
#pragma unroll
            for (int mi = 0; mi < 4; mi++)
#pragma unroll
                for (int nj = 0; nj < 4; nj++) {
                    mma_tf32(acc[mi][2 * nj + 0], afr[mi], &bfr[nj][0]);
                    mma_tf32(acc[mi][2 * nj + 1], afr[mi], &bfr[nj][2]);
                }
        }
    }

#pragma unroll
    for (int mi = 0; mi < 4; mi++) {
#pragma unroll
        for (int ni = 0; ni < 8; ni++) {
#pragma unroll
            for (int half = 0; half < 2; half++) {
                int m = m0 + warp_m + mi * 16 + r + half * 8;
                int nA = n0 + warp_n + ni * 8 + 2 * qc;
                float v0 = acc[mi][ni][half * 2 + 0] + bias[nA];
                float v1 = acc[mi][ni][half * 2 + 1] + bias[nA + 1];
                if (HEADS) {
                    int bb = m >> 11;
                    int tt = m & (NT - 1);
                    int h  = nA >> 6;
                    int hd = nA & (NHD - 1);
                    float* dst = outq +
                        (((size_t)bb * NH + h) * NT + tt) * NHD + hd;
                    dst[0] = v0; dst[1] = v1;
                } else {
                    float* dst = Cplain + (size_t)m * ND + nA;
                    dst[0] = v0; dst[1] = v1;
                }
            }
        }
    }
}

// ---------------------------------------------------------------------------
// Tensor-core tf32 flash attention, causal (R5 version, verbatim).
// CTA: 128 q rows, 8 warps x 16 rows. 64-key K/V tiles in smem (natural
// [key][dim] layout, stride 72 words -> all fragment reads conflict-free).
// P round-trips through warp-private smem slab (syncwarp only).
// ---------------------------------------------------------------------------
#define AST 72  /* smem row stride in words */
#define ATTN_SMEM ((64 + 64 + 128) * AST * 4)  /* 73728 B */

__global__ __launch_bounds__(256)
void attn_tc_kernel()
{
    extern __shared__ uint32_t smraw[];
    uint32_t (*Ks)[AST] = (uint32_t(*)[AST])smraw;
    uint32_t (*Vs)[AST] = (uint32_t(*)[AST])(smraw + 64 * AST);
    uint32_t (*Ps)[AST] = (uint32_t(*)[AST])(smraw + 128 * AST);

    const int bh   = blockIdx.y;
    const int q0   = blockIdx.x * 128;
    const int tid  = threadIdx.x;
    const int lane = tid & 31;
    const int warp = tid >> 5;
    const int r    = lane >> 2;    // 0..7
    const int c    = lane & 3;     // 0..3
    const int w16  = warp * 16;

    const float* Qb = g_q + (size_t)bh * NT * NHD;
    const float* Kb = g_k + (size_t)bh * NT * NHD;
    const float* Vb = g_v + (size_t)bh * NT * NHD;

    // ---- stage Q tile through Ps, pull A-fragments into registers ----
#pragma unroll
    for (int i = 0; i < 8; i++) {
        int idx = tid + i * 256;        // 0..2047
        int row = idx >> 4;             // 0..127
        int c4  = (idx & 15) * 4;
        float4 v = *(const float4*)(Qb + (size_t)(q0 + row) * NHD + c4);
        uint4 u;
        u.x = f2tf32(v.x); u.y = f2tf32(v.y);
        u.z = f2tf32(v.z); u.w = f2tf32(v.w);
        *(uint4*)&Ps[row][c4] = u;
    }
    __syncthreads();

    uint32_t qf[8][4];
#pragma unroll
    for (int kc = 0; kc < 8; kc++) {
        qf[kc][0] = Ps[w16 + r][kc * 8 + c];
        qf[kc][1] = Ps[w16 + r + 8][kc * 8 + c];
        qf[kc][2] = Ps[w16 + r][kc * 8 + c + 4];
        qf[kc][3] = Ps[w16 + r + 8][kc * 8 + c + 4];
    }
    __syncthreads();

    float o[8][4];
#pragma unroll
    for (int nt = 0; nt < 8; nt++)
#pragma unroll
        for (int e = 0; e < 4; e++) o[nt][e] = 0.f;

    float m0 = -1e30f, m1 = -1e30f, l0 = 0.f, l1 = 0.f;
    const int grow0 = q0 + w16 + r;
    const int grow1 = grow0 + 8;
    const float C2 = 0.18033688f;   // 0.125 * log2(e)

    const int ktiles = blockIdx.x * 2 + 2;
    for (int kt = 0; kt < ktiles; kt++) {
        const int kbase = kt * 64;
        __syncthreads();   // all warps done reading Ks/Vs from prev iter
#pragma unroll
        for (int i = 0; i < 4; i++) {
            int idx = tid + i * 256;    // 0..1023
            int row = idx >> 4;         // 0..63
            int c4  = (idx & 15) * 4;
            float4 kv = *(const float4*)(Kb + (size_t)(kbase + row) * NHD + c4);
            float4 vv = *(const float4*)(Vb + (size_t)(kbase + row) * NHD + c4);
            uint4 u;
            u.x = f2tf32(kv.x); u.y = f2tf32(kv.y);
            u.z = f2tf32(kv.z); u.w = f2tf32(kv.w);
            *(uint4*)&Ks[row][c4] = u;
            u.x = f2tf32(vv.x); u.y = f2tf32(vv.y);
            u.z = f2tf32(vv.z); u.w = f2tf32(vv.w);
            *(uint4*)&Vs[row][c4] = u;
        }
        __syncthreads();

        // ---- S = Q @ K^T  (warp's 16 rows x 64 keys) ----
        float sfr[8][4];
#pragma unroll
        for (int nt = 0; nt < 8; nt++) {
            sfr[nt][0] = sfr[nt][1] = sfr[nt][2] = sfr[nt][3] = 0.f;
#pragma unroll
            for (int kc = 0; kc < 8; kc++) {
                uint32_t b[2];
                b[0] = Ks[nt * 8 + r][kc * 8 + c];
                b[1] = Ks[nt * 8 + r][kc * 8 + c + 4];
                mma_tf32(sfr[nt], qf[kc], b);
            }
        }

        // ---- causal mask (only diagonal tiles of this warp) ----
        if (kbase + 63 > q0 + w16) {
#pragma unroll
            for (int nt = 0; nt < 8; nt++) {
                int col = kbase + nt * 8 + 2 * c;
                if (col > grow0)     sfr[nt][0] = -1e30f;
                if (col + 1 > grow0) sfr[nt][1] = -1e30f;
                if (col > grow1)     sfr[nt][2] = -1e30f;
                if (col + 1 > grow1) sfr[nt][3] = -1e30f;
            }
        }

        // ---- online softmax ----
        float mx0 = -1e30f, mx1 = -1e30f;
#pragma unroll
        for (int nt = 0; nt < 8; nt++) {
            mx0 = fmaxf(mx0, fmaxf(sfr[nt][0], sfr[nt][1]));
            mx1 = fmaxf(mx1, fmaxf(sfr[nt][2], sfr[nt][3]));
        }
        mx0 = fmaxf(mx0, __shfl_xor_sync(0xffffffffu, mx0, 1));
        mx0 = fmaxf(mx0, __shfl_xor_sync(0xffffffffu, mx0, 2));
        mx1 = fmaxf(mx1, __shfl_xor_sync(0xffffffffu, mx1, 1));
        mx1 = fmaxf(mx1, __shfl_xor_sync(0xffffffffu, mx1, 2));

        float mn0 = fmaxf(m0, mx0);
        float mn1 = fmaxf(m1, mx1);
        float cor0 = ex2((m0 - mn0) * C2);
        float cor1 = ex2((m1 - mn1) * C2);
        l0 *= cor0; l1 *= cor1;
        m0 = mn0;   m1 = mn1;

#pragma unroll
        for (int nt = 0; nt < 8; nt++) {
            float p0 = ex2((sfr[nt][0] - mn0) * C2);
            float p1 = ex2((sfr[nt][1] - mn0) * C2);
            float p2 = ex2((sfr[nt][2] - mn1) * C2);
            float p3 = ex2((sfr[nt][3] - mn1) * C2);
            l0 += p0 + p1;
            l1 += p2 + p3;
            o[nt][0] *= cor0; o[nt][1] *= cor0;
            o[nt][2] *= cor1; o[nt][3] *= cor1;
            uint2 w0; w0.x = f2tf32(p0); w0.y = f2tf32(p1);
            *(uint2*)&Ps[w16 + r][nt * 8 + 2 * c] = w0;
            uint2 w1; w1.x = f2tf32(p2); w1.y = f2tf32(p3);
            *(uint2*)&Ps[w16 + r + 8][nt * 8 + 2 * c] = w1;
        }
        __syncwarp();   // P slab is warp-private: no CTA barrier needed

        // ---- O += P @ V ----
#pragma unroll
        for (int kc = 0; kc < 8; kc++) {
            uint32_t a[4];
            a[0] = Ps[w16 + r][kc * 8 + c];
            a[1] = Ps[w16 + r + 8][kc * 8 + c];
            a[2] = Ps[w16 + r][kc * 8 + c + 4];
            a[3] = Ps[w16 + r + 8][kc * 8 + c + 4];
#pragma unroll
            for (int nt = 0; nt < 8; nt++) {
                uint32_t b[2];
                b[0] = Vs[kc * 8 + c][nt * 8 + r];
                b[1] = Vs[kc * 8 + c + 4][nt * 8 + r];
                mma_tf32(o[nt], a, b);
            }
        }
        __syncwarp();
    }

    // ---- quad-reduce softmax denominators (per-thread partials) ----
    l0 += __shfl_xor_sync(0xffffffffu, l0, 1);
    l0 += __shfl_xor_sync(0xffffffffu, l0, 2);
    l1 += __shfl_xor_sync(0xffffffffu, l1, 1);
    l1 += __shfl_xor_sync(0xffffffffu, l1, 2);

    // ---- normalize + store ----
    const int b  = bh >> 4;
    const int h  = bh & (NH - 1);
    float inv0 = 1.f / l0;
    float inv1 = 1.f / l1;
    float* y0 = g_y + ((size_t)b * NT + grow0) * ND + h * NHD;
    float* y1 = g_y + ((size_t)b * NT + grow1) * ND + h * NHD;
#pragma unroll
    for (int nt = 0; nt < 8; nt++) {
        float2 w0; w0.x = o[nt][0] * inv0; w0.y = o[nt][1] * inv0;
        *(float2*)(y0 + nt * 8 + 2 * c) = w0;
        float2 w1; w1.x = o[nt][2] * inv1; w1.y = o[nt][3] * inv1;
        *(float2*)(y1 + nt * 8 + 2 * c) = w1;
    }
}

// ---------------------------------------------------------------------------
extern "C" void kernel_launch(void* const* d_in, const int* in_sizes, int n_in,
                              void* d_out, int out_size)
{
    const float* x  = (const float*)d_in[0];
    const float* Wq = (const float*)d_in[1];
    const float* bq = (const float*)d_in[2];
    const float* Wk = (const float*)d_in[3];
    const float* bk = (const float*)d_in[4];
    const float* Wv = (const float*)d_in[5];
    const float* bv = (const float*)d_in[6];
    const float* Wp = (const float*)d_in[7];
    const float* bp = (const float*)d_in[8];
    float* out = (float*)d_out;

    cudaFuncSetAttribute(attn_tc_kernel,
                         cudaFuncAttributeMaxDynamicSharedMemorySize,
                         ATTN_SMEM);

    dim3 gq(ND / 128, NM / 128, 3);   // 8 x 32 x 3
    gemm_kernel<true><<<gq, 128>>>(x, Wq, bq, Wk, bk, Wv, bv, nullptr);

    dim3 ga(NT / 128, NB * NH);       // 16 x 32
    attn_tc_kernel<<<ga, 256, ATTN_SMEM>>>();

    dim3 gp(ND / 128, NM / 128, 1);   // 8 x 32
    gemm_kernel<false><<<gp, 128>>>(nullptr, Wp, bp, nullptr, nullptr,
                                    nullptr, nullptr, out);
}

// round 9
// speedup vs baseline: 1.3578x; 1.1172x over previous
#include <cuda_runtime.h>
#include <cstdint>

#define NB 2
#define NT 2048
#define ND 1024
#define NH 16
#define NHD 64
#define NM (NB * NT) /* 4096 rows */

// Scratch (device globals: allocation-free per harness rules)
__device__ float g_q[(size_t)NB * NH * NT * NHD];
__device__ float g_k[(size_t)NB * NH * NT * NHD];
__device__ float g_v[(size_t)NB * NH * NT * NHD];
__device__ float g_y[(size_t)NM * ND];

// ---------------------------------------------------------------------------
// tf32 / math helpers
// ---------------------------------------------------------------------------
__device__ __forceinline__ uint32_t f2tf32(float x) {
    uint32_t r;
    asm("cvt.rna.tf32.f32 %0, %1;" : "=r"(r) : "f"(x));
    return r;
}

__device__ __forceinline__ float ex2(float x) {
    float y;
    asm("ex2.approx.ftz.f32 %0, %1;" : "=f"(y) : "f"(x));
    return y;
}

__device__ __forceinline__ void mma_tf32(float* c, const uint32_t* a,
                                         const uint32_t* b) {
    asm volatile(
        "mma.sync.aligned.m16n8k8.row.col.f32.tf32.tf32.f32 "
        "{%0,%1,%2,%3}, {%4,%5,%6,%7}, {%8,%9}, {%0,%1,%2,%3};\n"
        : "+f"(c[0]), "+f"(c[1]), "+f"(c[2]), "+f"(c[3])
        : "r"(a[0]), "r"(a[1]), "r"(a[2]), "r"(a[3]), "r"(b[0]), "r"(b[1]));
}

// ldmatrix x4: four 8x8 b16 matrices == four 8x4 b32 matrices.
__device__ __forceinline__ void ldsm_x4(uint32_t* d, uint32_t addr) {
    asm volatile(
        "ldmatrix.sync.aligned.m8n8.x4.shared.b16 {%0,%1,%2,%3}, [%4];"
        : "=r"(d[0]), "=r"(d[1]), "=r"(d[2]), "=r"(d[3])
        : "r"(addr));
}

// ---------------------------------------------------------------------------
// tf32 tensor-core GEMM (R8, unchanged): C[m,n] = A[m,:]·W[n,:] + bias[n]
// CTA tile 128x128, K-step 16, 128 threads (4 warps, 2x2), warp tile 64x64,
// ldmatrix fragment loads, BKP=20 conflict-free.
// ---------------------------------------------------------------------------
#define BKP 20

template <bool HEADS>
__global__ __launch_bounds__(128, 2)
void gemm_kernel(const float* __restrict__ A,
                 const float* __restrict__ W0, const float* __restrict__ B0,
                 const float* __restrict__ W1, const float* __restrict__ B1,
                 const float* __restrict__ W2, const float* __restrict__ B2,
                 float* __restrict__ Cplain)
{
    const float* W;
    const float* bias;
    float* outq = nullptr;
    if (HEADS) {
        int z = blockIdx.z;
        W    = (z == 0) ? W0 : (z == 1) ? W1 : W2;
        bias = (z == 0) ? B0 : (z == 1) ? B1 : B2;
        outq = (z == 0) ? g_q : (z == 1) ? g_k : g_v;
    } else {
        W = W0; bias = B0;
    }
    const float* Ap = HEADS ? A : g_y;

    __shared__ uint32_t As[128][BKP];
    __shared__ uint32_t Bs[128][BKP];

    const int tid  = threadIdx.x;
    const int lane = tid & 31;
    const int wid  = tid >> 5;
    const int m0 = blockIdx.y * 128;
    const int n0 = blockIdx.x * 128;
    const int warp_m = (wid >> 1) * 64;
    const int warp_n = (wid & 1) * 64;
    const int r = lane >> 2;
    const int qc = lane & 3;

    const int g  = lane >> 3;
    const int lr = lane & 7;
    const uint32_t aBaseS =
        (uint32_t)__cvta_generic_to_shared(&As[0][0]);
    const uint32_t bBaseS =
        (uint32_t)__cvta_generic_to_shared(&Bs[0][0]);
    const uint32_t aAddr0 =
        aBaseS + (((warp_m + (g & 1) * 8 + lr) * BKP + (g >> 1) * 4) << 2);
    const uint32_t bAddr0 =
        bBaseS + (((warp_n + (g >> 1) * 8 + lr) * BKP + (g & 1) * 4) << 2);

    float acc[4][8][4];
#pragma unroll
    for (int mi = 0; mi < 4; mi++)
#pragma unroll
        for (int ni = 0; ni < 8; ni++)
#pragma unroll
            for (int e = 0; e < 4; e++) acc[mi][ni][e] = 0.f;

    const float* aBase = Ap + (size_t)m0 * ND;
    const float* wBase = W  + (size_t)n0 * ND;

    float4 pa[4], pb[4];
#pragma unroll
    for (int i = 0; i < 4; i++) {
        int idx = tid + i * 128;
        int row = idx >> 2;
        int c4  = (idx & 3) * 4;
        pa[i] = *(const float4*)(aBase + (size_t)row * ND + c4);
        pb[i] = *(const float4*)(wBase + (size_t)row * ND + c4);
    }

    for (int k0 = 0; k0 < ND; k0 += 16) {
        __syncthreads();
#pragma unroll
        for (int i = 0; i < 4; i++) {
            int idx = tid + i * 128;
            int row = idx >> 2;
            int c4  = (idx & 3) * 4;
            uint4 u;
            u.x = f2tf32(pa[i].x); u.y = f2tf32(pa[i].y);
            u.z = f2tf32(pa[i].z); u.w = f2tf32(pa[i].w);
            *(uint4*)&As[row][c4] = u;
            u.x = f2tf32(pb[i].x); u.y = f2tf32(pb[i].y);
            u.z = f2tf32(pb[i].z); u.w = f2tf32(pb[i].w);
            *(uint4*)&Bs[row][c4] = u;
        }
        __syncthreads();

        if (k0 + 16 < ND) {
            const int kn = k0 + 16;
#pragma unroll
            for (int i = 0; i < 4; i++) {
                int idx = tid + i * 128;
                int row = idx >> 2;
                int c4  = (idx & 3) * 4;
                pa[i] = *(const float4*)(aBase + (size_t)row * ND + kn + c4);
                pb[i] = *(const float4*)(wBase + (size_t)row * ND + kn + c4);
            }
        }

#pragma unroll
        for (int t = 0; t < 2; t++) {
            uint32_t afr[4][4], bfr[4][4];
#pragma unroll
            for (int mi = 0; mi < 4; mi++)
                ldsm_x4(afr[mi], aAddr0 + (uint32_t)(mi * 16 * BKP * 4 + t * 32));
#pragma unroll
            for (int nj = 0; nj < 4; nj++)
                ldsm_x4(bfr[nj], bAddr0 + (uint32_t)(nj * 16 * BKP * 4 + t * 32));
#pragma unroll
            for (int mi = 0; mi < 4; mi++)
#pragma unroll
                for (int nj = 0; nj < 4; nj++) {
                    mma_tf32(acc[mi][2 * nj + 0], afr[mi], &bfr[nj][0]);
                    mma_tf32(acc[mi][2 * nj + 1], afr[mi], &bfr[nj][2]);
                }
        }
    }

#pragma unroll
    for (int mi = 0; mi < 4; mi++) {
#pragma unroll
        for (int ni = 0; ni < 8; ni++) {
#pragma unroll
            for (int half = 0; half < 2; half++) {
                int m = m0 + warp_m + mi * 16 + r + half * 8;
                int nA = n0 + warp_n + ni * 8 + 2 * qc;
                float v0 = acc[mi][ni][half * 2 + 0] + bias[nA];
                float v1 = acc[mi][ni][half * 2 + 1] + bias[nA + 1];
                if (HEADS) {
                    int bb = m >> 11;
                    int tt = m & (NT - 1);
                    int h  = nA >> 6;
                    int hd = nA & (NHD - 1);
                    float* dst = outq +
                        (((size_t)bb * NH + h) * NT + tt) * NHD + hd;
                    dst[0] = v0; dst[1] = v1;
                } else {
                    float* dst = Cplain + (size_t)m * ND + nA;
                    dst[0] = v0; dst[1] = v1;
                }
            }
        }
    }
}

// ---------------------------------------------------------------------------
// Tensor-core tf32 flash attention, causal. R9: all fragment loads via
// ldmatrix (K, P, Q directly; V via transposed staging Vt[dim][key], since
// ldmatrix can't transpose b32). 288 LDS.32/tile/warp -> 72 ldsm_x4.
// AST 72->68 (==4 mod 32): conflict-free 8-row ldmatrix phases and
// conflict-free Vt STS.128 staging.
// ---------------------------------------------------------------------------
#define AST 68  /* smem row stride in words */
/* Ks: 64 rows, Vt: 64 rows, Ps: 128 rows */
#define ATTN_SMEM (256 * AST * 4)  /* 69632 B */

__global__ __launch_bounds__(256)
void attn_tc_kernel()
{
    extern __shared__ uint32_t smraw[];
    uint32_t (*Ks)[AST] = (uint32_t(*)[AST])smraw;
    uint32_t (*Vt)[AST] = (uint32_t(*)[AST])(smraw + 64 * AST);
    uint32_t (*Ps)[AST] = (uint32_t(*)[AST])(smraw + 128 * AST);

    const int bh   = blockIdx.y;
    const int q0   = blockIdx.x * 128;
    const int tid  = threadIdx.x;
    const int lane = tid & 31;
    const int warp = tid >> 5;
    const int r    = lane >> 2;    // 0..7
    const int c    = lane & 3;     // 0..3
    const int w16  = warp * 16;
    const int g    = lane >> 3;    // ldmatrix group
    const int lr   = lane & 7;

    const float* Qb = g_q + (size_t)bh * NT * NHD;
    const float* Kb = g_k + (size_t)bh * NT * NHD;
    const float* Vb = g_v + (size_t)bh * NT * NHD;

    const uint32_t psBase = (uint32_t)__cvta_generic_to_shared(&Ps[0][0]);
    const uint32_t ksBase = (uint32_t)__cvta_generic_to_shared(&Ks[0][0]);
    const uint32_t vtBase = (uint32_t)__cvta_generic_to_shared(&Vt[0][0]);
    // A-fragment ldsm address into Ps (used for Q and for P)
    const uint32_t aAddr =
        psBase + (((w16 + (g & 1) * 8 + lr) * AST + (g >> 1) * 4) << 2);
    // B-fragment ldsm address into Ks / Vt
    const uint32_t kAddr =
        ksBase + ((((g >> 1) * 8 + lr) * AST + (g & 1) * 4) << 2);
    const uint32_t vAddr =
        vtBase + ((((g >> 1) * 8 + lr) * AST + (g & 1) * 4) << 2);

    // ---- stage Q tile through Ps, pull A-fragments via ldsm ----
#pragma unroll
    for (int i = 0; i < 8; i++) {
        int idx = tid + i * 256;        // 0..2047
        int row = idx >> 4;             // 0..127
        int c4  = (idx & 15) * 4;
        float4 v = *(const float4*)(Qb + (size_t)(q0 + row) * NHD + c4);
        uint4 u;
        u.x = f2tf32(v.x); u.y = f2tf32(v.y);
        u.z = f2tf32(v.z); u.w = f2tf32(v.w);
        *(uint4*)&Ps[row][c4] = u;
    }
    __syncthreads();

    uint32_t qf[8][4];
#pragma unroll
    for (int kc = 0; kc < 8; kc++)
        ldsm_x4(qf[kc], aAddr + kc * 32);
    __syncthreads();

    float o[8][4];
#pragma unroll
    for (int nt = 0; nt < 8; nt++)
#pragma unroll
        for (int e = 0; e < 4; e++) o[nt][e] = 0.f;

    float m0 = -1e30f, m1 = -1e30f, l0 = 0.f, l1 = 0.f;
    const int grow0 = q0 + w16 + r;
    const int grow1 = grow0 + 8;
    const float C2 = 0.18033688f;   // 0.125 * log2(e)

    const int ktiles = blockIdx.x * 2 + 2;
    for (int kt = 0; kt < ktiles; kt++) {
        const int kbase = kt * 64;
        __syncthreads();   // all warps done reading Ks/Vt from prev iter
        // K natural [key][dim]
#pragma unroll
        for (int i = 0; i < 4; i++) {
            int idx = tid + i * 256;    // 0..1023
            int row = idx >> 4;         // 0..63
            int c4  = (idx & 15) * 4;
            float4 kv = *(const float4*)(Kb + (size_t)(kbase + row) * NHD + c4);
            uint4 u;
            u.x = f2tf32(kv.x); u.y = f2tf32(kv.y);
            u.z = f2tf32(kv.z); u.w = f2tf32(kv.w);
            *(uint4*)&Ks[row][c4] = u;
        }
        // V transposed: Vt[dim][key]; lane<->dim keeps LDGs coalesced,
        // STS.128 phases cover all 32 banks (AST==4 mod 32)
#pragma unroll
        for (int i = 0; i < 4; i++) {
            int s  = tid + i * 256;     // 0..1023
            int d  = s & 63;
            int k0 = (s >> 6) * 4;
            uint4 u;
            u.x = f2tf32(Vb[(size_t)(kbase + k0 + 0) * NHD + d]);
            u.y = f2tf32(Vb[(size_t)(kbase + k0 + 1) * NHD + d]);
            u.z = f2tf32(Vb[(size_t)(kbase + k0 + 2) * NHD + d]);
            u.w = f2tf32(Vb[(size_t)(kbase + k0 + 3) * NHD + d]);
            *(uint4*)&Vt[d][k0] = u;
        }
        __syncthreads();

        // ---- S = Q @ K^T  (warp's 16 rows x 64 keys), ldsm K-frags ----
        float sfr[8][4];
#pragma unroll
        for (int nt = 0; nt < 8; nt++)
            sfr[nt][0] = sfr[nt][1] = sfr[nt][2] = sfr[nt][3] = 0.f;
#pragma unroll
        for (int kc = 0; kc < 8; kc++) {
#pragma unroll
            for (int ng = 0; ng < 4; ng++) {
                uint32_t bk[4];
                ldsm_x4(bk, kAddr + (uint32_t)(ng * 16 * AST * 4 + kc * 32));
                mma_tf32(sfr[2 * ng + 0], qf[kc], &bk[0]);
                mma_tf32(sfr[2 * ng + 1], qf[kc], &bk[2]);
            }
        }

        // ---- causal mask (only diagonal tiles of this warp) ----
        if (kbase + 63 > q0 + w16) {
#pragma unroll
            for (int nt = 0; nt < 8; nt++) {
                int col = kbase + nt * 8 + 2 * c;
                if (col > grow0)     sfr[nt][0] = -1e30f;
                if (col + 1 > grow0) sfr[nt][1] = -1e30f;
                if (col > grow1)     sfr[nt][2] = -1e30f;
                if (col + 1 > grow1) sfr[nt][3] = -1e30f;
            }
        }

        // ---- online softmax ----
        float mx0 = -1e30f, mx1 = -1e30f;
#pragma unroll
        for (int nt = 0; nt < 8; nt++) {
            mx0 = fmaxf(mx0, fmaxf(sfr[nt][0], sfr[nt][1]));
            mx1 = fmaxf(mx1, fmaxf(sfr[nt][2], sfr[nt][3]));
        }
        mx0 = fmaxf(mx0, __shfl_xor_sync(0xffffffffu, mx0, 1));
        mx0 = fmaxf(mx0, __shfl_xor_sync(0xffffffffu, mx0, 2));
        mx1 = fmaxf(mx1, __shfl_xor_sync(0xffffffffu, mx1, 1));
        mx1 = fmaxf(mx1, __shfl_xor_sync(0xffffffffu, mx1, 2));

        float mn0 = fmaxf(m0, mx0);
        float mn1 = fmaxf(m1, mx1);
        float cor0 = ex2((m0 - mn0) * C2);
        float cor1 = ex2((m1 - mn1) * C2);
        l0 *= cor0; l1 *= cor1;
        m0 = mn0;   m1 = mn1;

#pragma unroll
        for (int nt = 0; nt < 8; nt++) {
            float p0 = ex2((sfr[nt][0] - mn0) * C2);
            float p1 = ex2((sfr[nt][1] - mn0) * C2);
            float p2 = ex2((sfr[nt][2] - mn1) * C2);
            float p3 = ex2((sfr[nt][3] - mn1) * C2);
            l0 += p0 + p1;
            l1 += p2 + p3;
            o[nt][0] *= cor0; o[nt][1] *= cor0;
            o[nt][2] *= cor1; o[nt][3] *= cor1;
            uint2 w0; w0.x = f2tf32(p0); w0.y = f2tf32(p1);
            *(uint2*)&Ps[w16 + r][nt * 8 + 2 * c] = w0;
            uint2 w1; w1.x = f2tf32(p2); w1.y = f2tf32(p3);
            *(uint2*)&Ps[w16 + r + 8][nt * 8 + 2 * c] = w1;
        }
        __syncwarp();   // P slab is warp-private: no CTA barrier needed

        // ---- O += P @ V : ldsm P A-frags + Vt B-frags ----
#pragma unroll
        for (int kc = 0; kc < 8; kc++) {
            uint32_t ap[4];
            ldsm_x4(ap, aAddr + kc * 32);
#pragma unroll
            for (int ng = 0; ng < 4; ng++) {
                uint32_t bv[4];
                ldsm_x4(bv, vAddr + (uint32_t)(ng * 16 * AST * 4 + kc * 32));
                mma_tf32(o[2 * ng + 0], ap, &bv[0]);
                mma_tf32(o[2 * ng + 1], ap, &bv[2]);
            }
        }
        __syncwarp();
    }

    // ---- quad-reduce softmax denominators (per-thread partials) ----
    l0 += __shfl_xor_sync(0xffffffffu, l0, 1);
    l0 += __shfl_xor_sync(0xffffffffu, l0, 2);
    l1 += __shfl_xor_sync(0xffffffffu, l1, 1);
    l1 += __shfl_xor_sync(0xffffffffu, l1, 2);

    // ---- normalize + store ----
    const int b  = bh >> 4;
    const int h  = bh & (NH - 1);
    float inv0 = 1.f / l0;
    float inv1 = 1.f / l1;
    float* y0 = g_y + ((size_t)b * NT + grow0) * ND + h * NHD;
    float* y1 = g_y + ((size_t)b * NT + grow1) * ND + h * NHD;
#pragma unroll
    for (int nt = 0; nt < 8; nt++) {
        float2 w0; w0.x = o[nt][0] * inv0; w0.y = o[nt][1] * inv0;
        *(float2*)(y0 + nt * 8 + 2 * c) = w0;
        float2 w1; w1.x = o[nt][2] * inv1; w1.y = o[nt][3] * inv1;
        *(float2*)(y1 + nt * 8 + 2 * c) = w1;
    }
}

// ---------------------------------------------------------------------------
extern "C" void kernel_launch(void* const* d_in, const int* in_sizes, int n_in,
                              void* d_out, int out_size)
{
    const float* x  = (const float*)d_in[0];
    const float* Wq = (const float*)d_in[1];
    const float* bq = (const float*)d_in[2];
    const float* Wk = (const float*)d_in[3];
    const float* bk = (const float*)d_in[4];
    const float* Wv = (const float*)d_in[5];
    const float* bv = (const float*)d_in[6];
    const float* Wp = (const float*)d_in[7];
    const float* bp = (const float*)d_in[8];
    float* out = (float*)d_out;

    cudaFuncSetAttribute(attn_tc_kernel,
                         cudaFuncAttributeMaxDynamicSharedMemorySize,
                         ATTN_SMEM);

    dim3 gq(ND / 128, NM / 128, 3);   // 8 x 32 x 3
    gemm_kernel<true><<<gq, 128>>>(x, Wq, bq, Wk, bk, Wv, bv, nullptr);

    dim3 ga(NT / 128, NB * NH);       // 16 x 32
    attn_tc_kernel<<<ga, 256, ATTN_SMEM>>>();

    dim3 gp(ND / 128, NM / 128, 1);   // 8 x 32
    gemm_kernel<false><<<gp, 128>>>(nullptr, Wp, bp, nullptr, nullptr,
                                    nullptr, nullptr, out);
}

// round 10
// speedup vs baseline: 1.3889x; 1.0229x over previous
#include <cuda_runtime.h>
#include <cstdint>

#define NB 2
#define NT 2048
#define ND 1024
#define NH 16
#define NHD 64
#define NM (NB * NT) /* 4096 rows */

// Scratch (device globals: allocation-free per harness rules)
__device__ float g_q[(size_t)NB * NH * NT * NHD];
__device__ float g_k[(size_t)NB * NH * NT * NHD];
__device__ float g_v[(size_t)NB * NH * NT * NHD];
__device__ float g_y[(size_t)NM * ND];

// ---------------------------------------------------------------------------
// tf32 / math helpers
// ---------------------------------------------------------------------------
__device__ __forceinline__ uint32_t f2tf32(float x) {
    uint32_t r;
    asm("cvt.rna.tf32.f32 %0, %1;" : "=r"(r) : "f"(x));
    return r;
}

__device__ __forceinline__ float ex2(float x) {
    float y;
    asm("ex2.approx.ftz.f32 %0, %1;" : "=f"(y) : "f"(x));
    return y;
}

__device__ __forceinline__ void mma_tf32(float* c, const uint32_t* a,
                                         const uint32_t* b) {
    asm volatile(
        "mma.sync.aligned.m16n8k8.row.col.f32.tf32.tf32.f32 "
        "{%0,%1,%2,%3}, {%4,%5,%6,%7}, {%8,%9}, {%0,%1,%2,%3};\n"
        : "+f"(c[0]), "+f"(c[1]), "+f"(c[2]), "+f"(c[3])
        : "r"(a[0]), "r"(a[1]), "r"(a[2]), "r"(a[3]), "r"(b[0]), "r"(b[1]));
}

// ldmatrix x4: four 8x8 b16 matrices == four 8x4 b32 matrices.
__device__ __forceinline__ void ldsm_x4(uint32_t* d, uint32_t addr) {
    asm volatile(
        "ldmatrix.sync.aligned.m8n8.x4.shared.b16 {%0,%1,%2,%3}, [%4];"
        : "=r"(d[0]), "=r"(d[1]), "=r"(d[2]), "=r"(d[3])
        : "r"(addr));
}

// ---------------------------------------------------------------------------
// tf32 tensor-core GEMM: C[m,n] = A[m,:]·W[n,:] + bias[n]
// CTA tile 128x128, K-step 16, 128 threads (4 warps, 2x2), warp tile 64x64,
// ldmatrix fragment loads, BKP=20 conflict-free.
// R10: double-buffered smem — one barrier per K-step, STS to buf^1 overlaps
// MMA on buf. HEADS epilogue pre-rounds outputs to tf32 (idempotent wrt the
// attn kernel's former cvt => bit-identical numerics downstream).
// ---------------------------------------------------------------------------
#define BKP 20
#define GBUF (128 * BKP * 4) /* 10240 B per buffer */

template <bool HEADS>
__global__ __launch_bounds__(128, 2)
void gemm_kernel(const float* __restrict__ A,
                 const float* __restrict__ W0, const float* __restrict__ B0,
                 const float* __restrict__ W1, const float* __restrict__ B1,
                 const float* __restrict__ W2, const float* __restrict__ B2,
                 float* __restrict__ Cplain)
{
    const float* W;
    const float* bias;
    float* outq = nullptr;
    if (HEADS) {
        int z = blockIdx.z;
        W    = (z == 0) ? W0 : (z == 1) ? W1 : W2;
        bias = (z == 0) ? B0 : (z == 1) ? B1 : B2;
        outq = (z == 0) ? g_q : (z == 1) ? g_k : g_v;
    } else {
        W = W0; bias = B0;
    }
    const float* Ap = HEADS ? A : g_y;

    __shared__ uint32_t As[2][128][BKP];
    __shared__ uint32_t Bs[2][128][BKP];

    const int tid  = threadIdx.x;
    const int lane = tid & 31;
    const int wid  = tid >> 5;
    const int m0 = blockIdx.y * 128;
    const int n0 = blockIdx.x * 128;
    const int warp_m = (wid >> 1) * 64;
    const int warp_n = (wid & 1) * 64;
    const int r = lane >> 2;
    const int qc = lane & 3;

    const int g  = lane >> 3;
    const int lr = lane & 7;
    const uint32_t aBaseS =
        (uint32_t)__cvta_generic_to_shared(&As[0][0][0]);
    const uint32_t bBaseS =
        (uint32_t)__cvta_generic_to_shared(&Bs[0][0][0]);
    const uint32_t aAddr0 =
        aBaseS + (((warp_m + (g & 1) * 8 + lr) * BKP + (g >> 1) * 4) << 2);
    const uint32_t bAddr0 =
        bBaseS + (((warp_n + (g >> 1) * 8 + lr) * BKP + (g & 1) * 4) << 2);

    float acc[4][8][4];
#pragma unroll
    for (int mi = 0; mi < 4; mi++)
#pragma unroll
        for (int ni = 0; ni < 8; ni++)
#pragma unroll
            for (int e = 0; e < 4; e++) acc[mi][ni][e] = 0.f;

    const float* aBase = Ap + (size_t)m0 * ND;
    const float* wBase = W  + (size_t)n0 * ND;

    const int srow = tid >> 2;          // staging row pair base (0..31)*? no:
    // staging: idx = tid + i*128 -> row = idx>>2 (0..127), c4 = (idx&3)*4
    float4 pa[4], pb[4];
#pragma unroll
    for (int i = 0; i < 4; i++) {
        int idx = tid + i * 128;
        int row = idx >> 2;
        int c4  = (idx & 3) * 4;
        pa[i] = *(const float4*)(aBase + (size_t)row * ND + c4);
        pb[i] = *(const float4*)(wBase + (size_t)row * ND + c4);
    }
    (void)srow;
    // stage tile 0 into buffer 0
#pragma unroll
    for (int i = 0; i < 4; i++) {
        int idx = tid + i * 128;
        int row = idx >> 2;
        int c4  = (idx & 3) * 4;
        uint4 u;
        u.x = f2tf32(pa[i].x); u.y = f2tf32(pa[i].y);
        u.z = f2tf32(pa[i].z); u.w = f2tf32(pa[i].w);
        *(uint4*)&As[0][row][c4] = u;
        u.x = f2tf32(pb[i].x); u.y = f2tf32(pb[i].y);
        u.z = f2tf32(pb[i].z); u.w = f2tf32(pb[i].w);
        *(uint4*)&Bs[0][row][c4] = u;
    }
    __syncthreads();

    int buf = 0;
    for (int k0 = 0; k0 < ND; k0 += 16) {
        const bool more = (k0 + 16 < ND);
        if (more) {
            const int kn = k0 + 16;
#pragma unroll
            for (int i = 0; i < 4; i++) {
                int idx = tid + i * 128;
                int row = idx >> 2;
                int c4  = (idx & 3) * 4;
                pa[i] = *(const float4*)(aBase + (size_t)row * ND + kn + c4);
                pb[i] = *(const float4*)(wBase + (size_t)row * ND + kn + c4);
            }
        }

        const uint32_t bofs = (uint32_t)buf * GBUF;
#pragma unroll
        for (int t = 0; t < 2; t++) {
            uint32_t afr[4][4], bfr[4][4];
#pragma unroll
            for (int mi = 0; mi < 4; mi++)
                ldsm_x4(afr[mi],
                        aAddr0 + bofs + (uint32_t)(mi * 16 * BKP * 4 + t * 32));
#pragma unroll
            for (int nj = 0; nj < 4; nj++)
                ldsm_x4(bfr[nj],
                        bAddr0 + bofs + (uint32_t)(nj * 16 * BKP * 4 + t * 32));
#pragma unroll
            for (int mi = 0; mi < 4; mi++)
#pragma unroll
                for (int nj = 0; nj < 4; nj++) {
                    mma_tf32(acc[mi][2 * nj + 0], afr[mi], &bfr[nj][0]);
                    mma_tf32(acc[mi][2 * nj + 1], afr[mi], &bfr[nj][2]);
                }
        }

        if (more) {
            const int nb = buf ^ 1;
#pragma unroll
            for (int i = 0; i < 4; i++) {
                int idx = tid + i * 128;
                int row = idx >> 2;
                int c4  = (idx & 3) * 4;
                uint4 u;
                u.x = f2tf32(pa[i].x); u.y = f2tf32(pa[i].y);
                u.z = f2tf32(pa[i].z); u.w = f2tf32(pa[i].w);
                *(uint4*)&As[nb][row][c4] = u;
                u.x = f2tf32(pb[i].x); u.y = f2tf32(pb[i].y);
                u.z = f2tf32(pb[i].z); u.w = f2tf32(pb[i].w);
                *(uint4*)&Bs[nb][row][c4] = u;
            }
            __syncthreads();
            buf = nb;
        }
    }

#pragma unroll
    for (int mi = 0; mi < 4; mi++) {
#pragma unroll
        for (int ni = 0; ni < 8; ni++) {
#pragma unroll
            for (int half = 0; half < 2; half++) {
                int m = m0 + warp_m + mi * 16 + r + half * 8;
                int nA = n0 + warp_n + ni * 8 + 2 * qc;
                float v0 = acc[mi][ni][half * 2 + 0] + bias[nA];
                float v1 = acc[mi][ni][half * 2 + 1] + bias[nA + 1];
                if (HEADS) {
                    int bb = m >> 11;
                    int tt = m & (NT - 1);
                    int h  = nA >> 6;
                    int hd = nA & (NHD - 1);
                    float* dst = outq +
                        (((size_t)bb * NH + h) * NT + tt) * NHD + hd;
                    // pre-round to tf32: idempotent wrt attn's former cvt
                    dst[0] = __uint_as_float(f2tf32(v0));
                    dst[1] = __uint_as_float(f2tf32(v1));
                } else {
                    float* dst = Cplain + (size_t)m * ND + nA;
                    dst[0] = v0; dst[1] = v1;
                }
            }
        }
    }
}

// ---------------------------------------------------------------------------
// Tensor-core tf32 flash attention, causal. ldmatrix everywhere (R9).
// R10: Q/K/V arrive pre-rounded to tf32 (GEMM epilogue) -> staging is pure
// bit-copy; next tile's K/V LDGs are register-prefetched right after the
// staging barrier so the L2 latency hides behind this tile's MMAs.
// ---------------------------------------------------------------------------
#define AST 68  /* smem row stride in words */
/* Ks: 64 rows, Vt: 64 rows, Ps: 128 rows */
#define ATTN_SMEM (256 * AST * 4)  /* 69632 B */

__global__ __launch_bounds__(256)
void attn_tc_kernel()
{
    extern __shared__ uint32_t smraw[];
    uint32_t (*Ks)[AST] = (uint32_t(*)[AST])smraw;
    uint32_t (*Vt)[AST] = (uint32_t(*)[AST])(smraw + 64 * AST);
    uint32_t (*Ps)[AST] = (uint32_t(*)[AST])(smraw + 128 * AST);

    const int bh   = blockIdx.y;
    const int q0   = blockIdx.x * 128;
    const int tid  = threadIdx.x;
    const int lane = tid & 31;
    const int warp = tid >> 5;
    const int r    = lane >> 2;    // 0..7
    const int c    = lane & 3;     // 0..3
    const int w16  = warp * 16;
    const int g    = lane >> 3;    // ldmatrix group
    const int lr   = lane & 7;

    const uint32_t* Qb = (const uint32_t*)g_q + (size_t)bh * NT * NHD;
    const uint32_t* Kb = (const uint32_t*)g_k + (size_t)bh * NT * NHD;
    const uint32_t* Vb = (const uint32_t*)g_v + (size_t)bh * NT * NHD;

    const uint32_t psBase = (uint32_t)__cvta_generic_to_shared(&Ps[0][0]);
    const uint32_t ksBase = (uint32_t)__cvta_generic_to_shared(&Ks[0][0]);
    const uint32_t vtBase = (uint32_t)__cvta_generic_to_shared(&Vt[0][0]);
    const uint32_t aAddr =
        psBase + (((w16 + (g & 1) * 8 + lr) * AST + (g >> 1) * 4) << 2);
    const uint32_t kAddr =
        ksBase + ((((g >> 1) * 8 + lr) * AST + (g & 1) * 4) << 2);
    const uint32_t vAddr =
        vtBase + ((((g >> 1) * 8 + lr) * AST + (g & 1) * 4) << 2);

    // ---- stage Q tile (pre-rounded bits) through Ps, ldsm A-frags ----
#pragma unroll
    for (int i = 0; i < 8; i++) {
        int idx = tid + i * 256;        // 0..2047
        int row = idx >> 4;             // 0..127
        int c4  = (idx & 15) * 4;
        *(uint4*)&Ps[row][c4] =
            *(const uint4*)(Qb + (size_t)(q0 + row) * NHD + c4);
    }
    __syncthreads();

    uint32_t qf[8][4];
#pragma unroll
    for (int kc = 0; kc < 8; kc++)
        ldsm_x4(qf[kc], aAddr + kc * 32);
    __syncthreads();

    float o[8][4];
#pragma unroll
    for (int nt = 0; nt < 8; nt++)
#pragma unroll
        for (int e = 0; e < 4; e++) o[nt][e] = 0.f;

    float m0 = -1e30f, m1 = -1e30f, l0 = 0.f, l1 = 0.f;
    const int grow0 = q0 + w16 + r;
    const int grow1 = grow0 + 8;
    const float C2 = 0.18033688f;   // 0.125 * log2(e)

    const int ktiles = blockIdx.x * 2 + 2;

    // per-thread staging coordinates
    const int kRow = tid >> 4;            // base K row (plus i*16)
    const int kC4  = (tid & 15) * 4;
    const int vD   = tid & 63;            // Vt: dim
    const int vK0  = (tid >> 6) * 4;      // Vt: key group base (plus i*16)

    // ---- prefetch tile 0 into registers ----
    uint4 kq[4];
    uint32_t vq[16];
#pragma unroll
    for (int i = 0; i < 4; i++) {
        kq[i] = *(const uint4*)(Kb + (size_t)(kRow + i * 16) * NHD + kC4);
#pragma unroll
        for (int j = 0; j < 4; j++)
            vq[i * 4 + j] = Vb[(size_t)(vK0 + i * 16 + j) * NHD + vD];
    }

    for (int kt = 0; kt < ktiles; kt++) {
        const int kbase = kt * 64;
        __syncthreads();   // all warps done reading Ks/Vt from prev tile
#pragma unroll
        for (int i = 0; i < 4; i++) {
            *(uint4*)&Ks[kRow + i * 16][kC4] = kq[i];
            uint4 u;
            u.x = vq[i * 4 + 0]; u.y = vq[i * 4 + 1];
            u.z = vq[i * 4 + 2]; u.w = vq[i * 4 + 3];
            *(uint4*)&Vt[vD][vK0 + i * 16] = u;
        }
        __syncthreads();

        // ---- prefetch next tile (latency hidden behind MMAs below) ----
        if (kt + 1 < ktiles) {
            const int nb0 = kbase + 64;
#pragma unroll
            for (int i = 0; i < 4; i++) {
                kq[i] = *(const uint4*)(Kb +
                        (size_t)(nb0 + kRow + i * 16) * NHD + kC4);
#pragma unroll
                for (int j = 0; j < 4; j++)
                    vq[i * 4 + j] =
                        Vb[(size_t)(nb0 + vK0 + i * 16 + j) * NHD + vD];
            }
        }

        // ---- S = Q @ K^T  (warp's 16 rows x 64 keys), ldsm K-frags ----
        float sfr[8][4];
#pragma unroll
        for (int nt = 0; nt < 8; nt++)
            sfr[nt][0] = sfr[nt][1] = sfr[nt][2] = sfr[nt][3] = 0.f;
#pragma unroll
        for (int kc = 0; kc < 8; kc++) {
#pragma unroll
            for (int ng = 0; ng < 4; ng++) {
                uint32_t bk[4];
                ldsm_x4(bk, kAddr + (uint32_t)(ng * 16 * AST * 4 + kc * 32));
                mma_tf32(sfr[2 * ng + 0], qf[kc], &bk[0]);
                mma_tf32(sfr[2 * ng + 1], qf[kc], &bk[2]);
            }
        }

        // ---- causal mask (only diagonal tiles of this warp) ----
        if (kbase + 63 > q0 + w16) {
#pragma unroll
            for (int nt = 0; nt < 8; nt++) {
                int col = kbase + nt * 8 + 2 * c;
                if (col > grow0)     sfr[nt][0] = -1e30f;
                if (col + 1 > grow0) sfr[nt][1] = -1e30f;
                if (col > grow1)     sfr[nt][2] = -1e30f;
                if (col + 1 > grow1) sfr[nt][3] = -1e30f;
            }
        }

        // ---- online softmax ----
        float mx0 = -1e30f, mx1 = -1e30f;
#pragma unroll
        for (int nt = 0; nt < 8; nt++) {
            mx0 = fmaxf(mx0, fmaxf(sfr[nt][0], sfr[nt][1]));
            mx1 = fmaxf(mx1, fmaxf(sfr[nt][2], sfr[nt][3]));
        }
        mx0 = fmaxf(mx0, __shfl_xor_sync(0xffffffffu, mx0, 1));
        mx0 = fmaxf(mx0, __shfl_xor_sync(0xffffffffu, mx0, 2));
        mx1 = fmaxf(mx1, __shfl_xor_sync(0xffffffffu, mx1, 1));
        mx1 = fmaxf(mx1, __shfl_xor_sync(0xffffffffu, mx1, 2));

        float mn0 = fmaxf(m0, mx0);
        float mn1 = fmaxf(m1, mx1);
        float cor0 = ex2((m0 - mn0) * C2);
        float cor1 = ex2((m1 - mn1) * C2);
        l0 *= cor0; l1 *= cor1;
        m0 = mn0;   m1 = mn1;

#pragma unroll
        for (int nt = 0; nt < 8; nt++) {
            float p0 = ex2((sfr[nt][0] - mn0) * C2);
            float p1 = ex2((sfr[nt][1] - mn0) * C2);
            float p2 = ex2((sfr[nt][2] - mn1) * C2);
            float p3 = ex2((sfr[nt][3] - mn1) * C2);
            l0 += p0 + p1;
            l1 += p2 + p3;
            o[nt][0] *= cor0; o[nt][1] *= cor0;
            o[nt][2] *= cor1; o[nt][3] *= cor1;
            uint2 w0; w0.x = f2tf32(p0); w0.y = f2tf32(p1);
            *(uint2*)&Ps[w16 + r][nt * 8 + 2 * c] = w0;
            uint2 w1; w1.x = f2tf32(p2); w1.y = f2tf32(p3);
            *(uint2*)&Ps[w16 + r + 8][nt * 8 + 2 * c] = w1;
        }
        __syncwarp();   // P slab is warp-private: no CTA barrier needed

        // ---- O += P @ V : ldsm P A-frags + Vt B-frags ----
#pragma unroll
        for (int kc = 0; kc < 8; kc++) {
            uint32_t ap[4];
            ldsm_x4(ap, aAddr + kc * 32);
#pragma unroll
            for (int ng = 0; ng < 4; ng++) {
                uint32_t bv[4];
                ldsm_x4(bv, vAddr + (uint32_t)(ng * 16 * AST * 4 + kc * 32));
                mma_tf32(o[2 * ng + 0], ap, &bv[0]);
                mma_tf32(o[2 * ng + 1], ap, &bv[2]);
            }
        }
        __syncwarp();
    }

    // ---- quad-reduce softmax denominators (per-thread partials) ----
    l0 += __shfl_xor_sync(0xffffffffu, l0, 1);
    l0 += __shfl_xor_sync(0xffffffffu, l0, 2);
    l1 += __shfl_xor_sync(0xffffffffu, l1, 1);
    l1 += __shfl_xor_sync(0xffffffffu, l1, 2);

    // ---- normalize + store ----
    const int b  = bh >> 4;
    const int h  = bh & (NH - 1);
    float inv0 = 1.f / l0;
    float inv1 = 1.f / l1;
    float* y0 = g_y + ((size_t)b * NT + grow0) * ND + h * NHD;
    float* y1 = g_y + ((size_t)b * NT + grow1) * ND + h * NHD;
#pragma unroll
    for (int nt = 0; nt < 8; nt++) {
        float2 w0; w0.x = o[nt][0] * inv0; w0.y = o[nt][1] * inv0;
        *(float2*)(y0 + nt * 8 + 2 * c) = w0;
        float2 w1; w1.x = o[nt][2] * inv1; w1.y = o[nt][3] * inv1;
        *(float2*)(y1 + nt * 8 + 2 * c) = w1;
    }
}

// ---------------------------------------------------------------------------
extern "C" void kernel_launch(void* const* d_in, const int* in_sizes, int n_in,
                              void* d_out, int out_size)
{
    const float* x  = (const float*)d_in[0];
    const float* Wq = (const float*)d_in[1];
    const float* bq = (const float*)d_in[2];
    const float* Wk = (const float*)d_in[3];
    const float* bk = (const float*)d_in[4];
    const float* Wv = (const float*)d_in[5];
    const float* bv = (const float*)d_in[6];
    const float* Wp = (const float*)d_in[7];
    const float* bp = (const float*)d_in[8];
    float* out = (float*)d_out;

    cudaFuncSetAttribute(attn_tc_kernel,
                         cudaFuncAttributeMaxDynamicSharedMemorySize,
                         ATTN_SMEM);

    dim3 gq(ND / 128, NM / 128, 3);   // 8 x 32 x 3
    gemm_kernel<true><<<gq, 128>>>(x, Wq, bq, Wk, bk, Wv, bv, nullptr);

    dim3 ga(NT / 128, NB * NH);       // 16 x 32
    attn_tc_kernel<<<ga, 256, ATTN_SMEM>>>();

    dim3 gp(ND / 128, NM / 128, 1);   // 8 x 32
    gemm_kernel<false><<<gp, 128>>>(nullptr, Wp, bp, nullptr, nullptr,
                                    nullptr, nullptr, out);
}